// round 5
// baseline (speedup 1.0000x reference)
#include <cuda_runtime.h>

#define Hh 1024
#define Ww 1024
#define Bb 16
#define DIL 2
#define NTHREADS 256
#define RPB 32                              // rows per block strip
#define BLKS_PER_IMG (Hh / RPB)             // 32
#define NBLOCKS (Bb * BLKS_PER_IMG)         // 512
#define NELEM ((long long)Bb * Hh * Ww)

__device__ double       g_sum   = 0.0;
__device__ unsigned int g_count = 0u;

// Assemble the 8-wide window data[x4-2 .. x4+5] for row gy from three aligned
// float4 global loads, with zero-padding at image borders (top/bottom/left/right).
__device__ __forceinline__ void load_winG(float w[8], const float* __restrict__ img,
                                          int gy, int x4, bool leftEdge, bool rightEdge) {
    float4 L = make_float4(0.f, 0.f, 0.f, 0.f);
    float4 C = L, R = L;
    if (gy >= 0 && gy < Hh) {                       // uniform across the warp
        const float* r = img + (size_t)gy * Ww;
        if (!leftEdge)  L = *reinterpret_cast<const float4*>(r + x4 - 4);
        C = *reinterpret_cast<const float4*>(r + x4);
        if (!rightEdge) R = *reinterpret_cast<const float4*>(r + x4 + 4);
    }
    w[0] = L.z; w[1] = L.w;
    w[2] = C.x; w[3] = C.y; w[4] = C.z; w[5] = C.w;
    w[6] = R.x; w[7] = R.y;
}

__global__ __launch_bounds__(NTHREADS, 4)
void consistency_main(const float* __restrict__ yt, const float* __restrict__ yp,
                      float* __restrict__ out) {
    __shared__ float warp_sums[NTHREADS / 32];

    const int blk = blockIdx.x;                     // 0..511
    const int b   = blk >> 5;                       // image
    const int yg  = (blk & (BLKS_PER_IMG - 1)) * RPB;
    const int tid = threadIdx.x;
    const int x4  = tid * 4;
    const bool leftEdge  = (tid == 0);
    const bool rightEdge = (tid == NTHREADS - 1);

    const float* img  = yp + (size_t)b * Hh * Ww;
    const float* timg = yt + (size_t)b * Hh * Ww;

    float lsum = 0.f;

    // Two parity chains (rows yg+c, yg+c+2, ...): vertical neighbors are +-2,
    // so each chain rolls three 8-wide register windows down its rows.
#pragma unroll 1
    for (int c = 0; c < 2; ++c) {
        float w0[8], w1[8], w2[8];
        load_winG(w0, img, yg + c - 2, x4, leftEdge, rightEdge);
        load_winG(w1, img, yg + c,     x4, leftEdge, rightEdge);

#pragma unroll 1
        for (int j = c; j < RPB; j += 2) {
            load_winG(w2, img, yg + j + 2, x4, leftEdge, rightEdge);
            const float4 t4 = *reinterpret_cast<const float4*>(
                timg + (size_t)(yg + j) * Ww + x4);
            const float tval[4] = { t4.x, t4.y, t4.z, t4.w };

#pragma unroll
            for (int k = 0; k < 4; ++k) {
                const float p = w1[k + 2];
                const float t = tval[k];

                float lp = fmaxf(__logf(p),        -100.0f);
                float l1 = fmaxf(__logf(1.0f - p), -100.0f);
                float a  = -(t * lp + (1.0f - t) * l1);

                float uw;
                uw =           fabsf(p - w0[k]);
                uw = fmaxf(uw, fabsf(p - w0[k + 2]));
                uw = fmaxf(uw, fabsf(p - w0[k + 4]));
                uw = fmaxf(uw, fabsf(p - w1[k]));
                uw = fmaxf(uw, fabsf(p - w1[k + 4]));
                uw = fmaxf(uw, fabsf(p - w2[k]));
                uw = fmaxf(uw, fabsf(p - w2[k + 2]));
                uw = fmaxf(uw, fabsf(p - w2[k + 4]));

                const float thred = (p >= 0.5f) ? p : 0.0f;
                lsum += fmaf(uw, thred, a);
            }
#pragma unroll
            for (int q = 0; q < 8; ++q) { w0[q] = w1[q]; w1[q] = w2[q]; }
        }
    }

    // Block reduction
#pragma unroll
    for (int off = 16; off > 0; off >>= 1)
        lsum += __shfl_xor_sync(0xFFFFFFFFu, lsum, off);
    if ((tid & 31) == 0) warp_sums[tid >> 5] = lsum;
    __syncthreads();
    if (tid == 0) {
        float v = 0.f;
#pragma unroll
        for (int w = 0; w < NTHREADS / 32; ++w) v += warp_sums[w];

        // Fused final reduction: last-arriving block writes the mean.
        atomicAdd(&g_sum, (double)v);
        __threadfence();
        const unsigned int old = atomicAdd(&g_count, 1u);
        if (old == NBLOCKS - 1) {
            const double total = atomicAdd(&g_sum, 0.0);   // coherent read
            out[0] = (float)(total / (double)NELEM);
            g_sum   = 0.0;                                  // reset for next replay
            __threadfence();
            g_count = 0u;
        }
    }
}

extern "C" void kernel_launch(void* const* d_in, const int* in_sizes, int n_in,
                              void* d_out, int out_size) {
    const float* y_true = (const float*)d_in[0];
    const float* y_pred = (const float*)d_in[1];
    float* out = (float*)d_out;
    consistency_main<<<NBLOCKS, NTHREADS>>>(y_true, y_pred, out);
}

// round 6
// speedup vs baseline: 1.0008x; 1.0008x over previous
#include <cuda_runtime.h>

#define Hh 1024
#define Ww 1024
#define Bb 16
#define DIL 2
#define NTHREADS 256
#define RPB 16                              // rows per block strip
#define BLKS_PER_IMG (Hh / RPB)             // 64
#define NBLOCKS (Bb * BLKS_PER_IMG)         // 1024
#define NELEM ((long long)Bb * Hh * Ww)

__device__ double       g_sum   = 0.0;
__device__ unsigned int g_count = 0u;

// Assemble the 8-wide window data[x4-2 .. x4+5] for row gy from three aligned
// float4 global loads, zero-padded at image borders.
__device__ __forceinline__ void load_winG(float w[8], const float* __restrict__ img,
                                          int gy, int x4, bool leftEdge, bool rightEdge) {
    float4 L = make_float4(0.f, 0.f, 0.f, 0.f);
    float4 C = L, R = L;
    if (gy >= 0 && gy < Hh) {                       // uniform across the warp
        const float* r = img + (size_t)gy * Ww;
        if (!leftEdge)  L = *reinterpret_cast<const float4*>(r + x4 - 4);
        C = *reinterpret_cast<const float4*>(r + x4);
        if (!rightEdge) R = *reinterpret_cast<const float4*>(r + x4 + 4);
    }
    w[0] = L.z; w[1] = L.w;
    w[2] = C.x; w[3] = C.y; w[4] = C.z; w[5] = C.w;
    w[6] = R.x; w[7] = R.y;
}

// One output row: 4 pixels using windows (up, mid, dn) and y_true float4.
__device__ __forceinline__ float row_loss(const float up[8], const float mid[8],
                                          const float dn[8], float4 t4) {
    const float tval[4] = { t4.x, t4.y, t4.z, t4.w };
    float s = 0.f;
#pragma unroll
    for (int k = 0; k < 4; ++k) {
        const float p = mid[k + 2];
        const float t = tval[k];

        const float lp = fmaxf(__logf(p),        -100.0f);
        const float l1 = fmaxf(__logf(1.0f - p), -100.0f);
        const float a  = fmaf(t, l1 - lp, -l1);   // == -(t*lp + (1-t)*l1)

        float uw;
        uw =           fabsf(p - up[k]);
        uw = fmaxf(uw, fabsf(p - up[k + 2]));
        uw = fmaxf(uw, fabsf(p - up[k + 4]));
        uw = fmaxf(uw, fabsf(p - mid[k]));
        uw = fmaxf(uw, fabsf(p - mid[k + 4]));
        uw = fmaxf(uw, fabsf(p - dn[k]));
        uw = fmaxf(uw, fabsf(p - dn[k + 2]));
        uw = fmaxf(uw, fabsf(p - dn[k + 4]));

        const float thred = (p >= 0.5f) ? p : 0.0f;
        s += fmaf(uw, thred, a);
    }
    return s;
}

__global__ __launch_bounds__(NTHREADS, 4)
void consistency_main(const float* __restrict__ yt, const float* __restrict__ yp,
                      float* __restrict__ out) {
    __shared__ float warp_sums[NTHREADS / 32];

    const int blk = blockIdx.x;                     // 0..1023
    const int b   = blk >> 6;                       // image
    const int yg  = (blk & (BLKS_PER_IMG - 1)) * RPB;
    const int tid = threadIdx.x;
    const int x4  = tid * 4;
    const bool leftEdge  = (tid == 0);
    const bool rightEdge = (tid == NTHREADS - 1);

    const float* img  = yp + (size_t)b * Hh * Ww;
    const float* timg = yt + (size_t)b * Hh * Ww;

    float lsum = 0.f;

    // Two parity chains; each double-step processes rows j and j+2 of the chain,
    // front-batching 8 independent LDG.128 (6 window + 2 y_true) for MLP.
#pragma unroll 1
    for (int c = 0; c < 2; ++c) {
        float w0[8], w1[8], w2[8], w3[8];
        load_winG(w0, img, yg + c - 2, x4, leftEdge, rightEdge);
        load_winG(w1, img, yg + c,     x4, leftEdge, rightEdge);

#pragma unroll 1
        for (int j = c; j < RPB; j += 4) {
            load_winG(w2, img, yg + j + 2, x4, leftEdge, rightEdge);
            load_winG(w3, img, yg + j + 4, x4, leftEdge, rightEdge);
            const float4 tA = *reinterpret_cast<const float4*>(
                timg + (size_t)(yg + j) * Ww + x4);
            const float4 tB = *reinterpret_cast<const float4*>(
                timg + (size_t)(yg + j + 2) * Ww + x4);

            lsum += row_loss(w0, w1, w2, tA);       // row j
            lsum += row_loss(w1, w2, w3, tB);       // row j+2

#pragma unroll
            for (int q = 0; q < 8; ++q) { w0[q] = w2[q]; w1[q] = w3[q]; }
        }
    }

    // Block reduction
#pragma unroll
    for (int off = 16; off > 0; off >>= 1)
        lsum += __shfl_xor_sync(0xFFFFFFFFu, lsum, off);
    if ((tid & 31) == 0) warp_sums[tid >> 5] = lsum;
    __syncthreads();
    if (tid == 0) {
        float v = 0.f;
#pragma unroll
        for (int w = 0; w < NTHREADS / 32; ++w) v += warp_sums[w];

        // Fused final reduction: last-arriving block writes the mean.
        atomicAdd(&g_sum, (double)v);
        __threadfence();
        const unsigned int old = atomicAdd(&g_count, 1u);
        if (old == NBLOCKS - 1) {
            const double total = atomicAdd(&g_sum, 0.0);   // coherent read
            out[0] = (float)(total / (double)NELEM);
            g_sum   = 0.0;                                  // reset for next replay
            __threadfence();
            g_count = 0u;
        }
    }
}

extern "C" void kernel_launch(void* const* d_in, const int* in_sizes, int n_in,
                              void* d_out, int out_size) {
    const float* y_true = (const float*)d_in[0];
    const float* y_pred = (const float*)d_in[1];
    float* out = (float*)d_out;
    consistency_main<<<NBLOCKS, NTHREADS>>>(y_true, y_pred, out);
}

// round 7
// speedup vs baseline: 1.1242x; 1.1233x over previous
#include <cuda_runtime.h>

#define Hh 1024
#define Ww 1024
#define Bb 16
#define DIL 2
#define NTHREADS 256
#define RPB 16                              // rows per block strip
#define BLKS_PER_IMG (Hh / RPB)             // 64
#define NBLOCKS (Bb * BLKS_PER_IMG)         // 1024
#define NELEM ((long long)Bb * Hh * Ww)

#define NEG100_LG2 (-144.269504088896f)     // -100 / ln(2)
#define LN2F (0.6931471805599453f)

__device__ double       g_sum   = 0.0;
__device__ unsigned int g_count = 0u;

// Assemble the 8-wide window data[x4-2 .. x4+5] for row gy from three aligned
// float4 global loads, zero-padded at image borders.
__device__ __forceinline__ void load_winG(float w[8], const float* __restrict__ img,
                                          int gy, int x4, bool leftEdge, bool rightEdge) {
    float4 L = make_float4(0.f, 0.f, 0.f, 0.f);
    float4 C = L, R = L;
    if (gy >= 0 && gy < Hh) {                       // uniform across the warp
        const float* r = img + (size_t)gy * Ww;
        if (!leftEdge)  L = *reinterpret_cast<const float4*>(r + x4 - 4);
        C = *reinterpret_cast<const float4*>(r + x4);
        if (!rightEdge) R = *reinterpret_cast<const float4*>(r + x4 + 4);
    }
    w[0] = L.z; w[1] = L.w;
    w[2] = C.x; w[3] = C.y; w[4] = C.z; w[5] = C.w;
    w[6] = R.x; w[7] = R.y;
}

// One output row: 4 pixels. uw_acc += uw*thred ; bce_acc += t*(L1-Lp) - L1 (lg2 units).
__device__ __forceinline__ void row_loss(const float up[8], const float mid[8],
                                         const float dn[8], float4 t4,
                                         float& uw_acc, float& bce_acc) {
    // Shared column reductions over the vertical pair (up, dn)
    float cmn[8], cmx[8];
#pragma unroll
    for (int x = 0; x < 8; ++x) {
        cmn[x] = fminf(up[x], dn[x]);
        cmx[x] = fmaxf(up[x], dn[x]);
    }
    const float tval[4] = { t4.x, t4.y, t4.z, t4.w };
#pragma unroll
    for (int k = 0; k < 4; ++k) {
        const float p = mid[k + 2];
        const float t = tval[k];

        // neighbor min / max over {(y+-2, x-2|x|x+2), (y, x-2|x+2)}
        const float mn = fminf(fminf(fminf(cmn[k], mid[k]),
                                     fminf(cmn[k + 4], mid[k + 4])),
                               cmn[k + 2]);
        const float mx = fmaxf(fmaxf(fmaxf(cmx[k], mid[k]),
                                     fmaxf(cmx[k + 4], mid[k + 4])),
                               cmx[k + 2]);
        const float uw = fmaxf(p - mn, mx - p);     // == max_nb |p - nb|

        const float thred = (p >= 0.5f) ? p : 0.0f;
        uw_acc = fmaf(uw, thred, uw_acc);

        // BCE in lg2 domain
        const float Lp = fmaxf(__log2f(p),        NEG100_LG2);
        const float L1 = fmaxf(__log2f(1.0f - p), NEG100_LG2);
        bce_acc = fmaf(t, L1 - Lp, bce_acc - L1);
    }
}

__global__ __launch_bounds__(NTHREADS, 4)
void consistency_main(const float* __restrict__ yt, const float* __restrict__ yp,
                      float* __restrict__ out) {
    __shared__ float warp_sums[NTHREADS / 32];

    const int blk = blockIdx.x;                     // 0..1023
    const int b   = blk >> 6;                       // image
    const int yg  = (blk & (BLKS_PER_IMG - 1)) * RPB;
    const int tid = threadIdx.x;
    const int x4  = tid * 4;
    const bool leftEdge  = (tid == 0);
    const bool rightEdge = (tid == NTHREADS - 1);

    const float* img  = yp + (size_t)b * Hh * Ww;
    const float* timg = yt + (size_t)b * Hh * Ww;

    float uw_acc  = 0.f;
    float bce_acc = 0.f;

    // Two parity chains; each double-step handles chain rows j and j+2 with
    // 8 front-batched LDG.128 (6 window + 2 y_true).
#pragma unroll 1
    for (int c = 0; c < 2; ++c) {
        float w0[8], w1[8], w2[8], w3[8];
        load_winG(w0, img, yg + c - 2, x4, leftEdge, rightEdge);
        load_winG(w1, img, yg + c,     x4, leftEdge, rightEdge);

#pragma unroll 1
        for (int j = c; j < RPB; j += 4) {
            load_winG(w2, img, yg + j + 2, x4, leftEdge, rightEdge);
            load_winG(w3, img, yg + j + 4, x4, leftEdge, rightEdge);
            const float4 tA = *reinterpret_cast<const float4*>(
                timg + (size_t)(yg + j) * Ww + x4);
            const float4 tB = *reinterpret_cast<const float4*>(
                timg + (size_t)(yg + j + 2) * Ww + x4);

            row_loss(w0, w1, w2, tA, uw_acc, bce_acc);   // row j
            row_loss(w1, w2, w3, tB, uw_acc, bce_acc);   // row j+2

#pragma unroll
            for (int q = 0; q < 8; ++q) { w0[q] = w2[q]; w1[q] = w3[q]; }
        }
    }

    float lsum = fmaf(LN2F, bce_acc, uw_acc);       // fold ln2 once

    // Block reduction
#pragma unroll
    for (int off = 16; off > 0; off >>= 1)
        lsum += __shfl_xor_sync(0xFFFFFFFFu, lsum, off);
    if ((tid & 31) == 0) warp_sums[tid >> 5] = lsum;
    __syncthreads();
    if (tid == 0) {
        float v = 0.f;
#pragma unroll
        for (int w = 0; w < NTHREADS / 32; ++w) v += warp_sums[w];

        // Fused final reduction: last-arriving block writes the mean.
        atomicAdd(&g_sum, (double)v);
        __threadfence();
        const unsigned int old = atomicAdd(&g_count, 1u);
        if (old == NBLOCKS - 1) {
            const double total = atomicAdd(&g_sum, 0.0);   // coherent read
            out[0] = (float)(total / (double)NELEM);
            g_sum   = 0.0;                                  // reset for next replay
            __threadfence();
            g_count = 0u;
        }
    }
}

extern "C" void kernel_launch(void* const* d_in, const int* in_sizes, int n_in,
                              void* d_out, int out_size) {
    const float* y_true = (const float*)d_in[0];
    const float* y_pred = (const float*)d_in[1];
    float* out = (float*)d_out;
    consistency_main<<<NBLOCKS, NTHREADS>>>(y_true, y_pred, out);
}

// round 8
// speedup vs baseline: 1.1923x; 1.0606x over previous
#include <cuda_runtime.h>

#define Hh 1024
#define Ww 1024
#define Bb 16
#define DIL 2
#define NTHREADS 256
#define RPB 16                              // rows per block strip
#define BLKS_PER_IMG (Hh / RPB)             // 64
#define NBLOCKS (Bb * BLKS_PER_IMG)         // 1024
#define NELEM ((long long)Bb * Hh * Ww)

#define NEG100_LG2 (-144.269504088896f)     // -100 / ln(2)
#define LN2F (0.6931471805599453f)

__device__ double       g_sum   = 0.0;
__device__ unsigned int g_count = 0u;

// Assemble the 8-wide window data[x4-2 .. x4+5] for row gy from three aligned
// float4 global loads, zero-padded at image borders.
__device__ __forceinline__ void load_winG(float w[8], const float* __restrict__ img,
                                          int gy, int x4, bool leftEdge, bool rightEdge) {
    float4 L = make_float4(0.f, 0.f, 0.f, 0.f);
    float4 C = L, R = L;
    if (gy >= 0 && gy < Hh) {                       // uniform across the warp
        const float* r = img + (size_t)gy * Ww;
        if (!leftEdge)  L = *reinterpret_cast<const float4*>(r + x4 - 4);
        C = *reinterpret_cast<const float4*>(r + x4);
        if (!rightEdge) R = *reinterpret_cast<const float4*>(r + x4 + 4);
    }
    w[0] = L.z; w[1] = L.w;
    w[2] = C.x; w[3] = C.y; w[4] = C.z; w[5] = C.w;
    w[6] = R.x; w[7] = R.y;
}

// One output row (4 px). Accumulators:
//   uw_acc   += max_nb|p-nb| * thred
//   a_tLp    += t * Lp        (lg2 units)
//   a_tL1    += t * L1
//   a_L1     += L1
__device__ __forceinline__ void row_loss(const float up[8], const float mid[8],
                                         const float dn[8], float4 t4,
                                         float& uw_acc, float& a_tLp,
                                         float& a_tL1, float& a_L1) {
    float cmn[8], cmx[8];
#pragma unroll
    for (int x = 0; x < 8; ++x) {
        cmn[x] = fminf(up[x], dn[x]);
        cmx[x] = fmaxf(up[x], dn[x]);
    }
    const float tval[4] = { t4.x, t4.y, t4.z, t4.w };
#pragma unroll
    for (int k = 0; k < 4; ++k) {
        const float p = mid[k + 2];
        const float t = tval[k];

        const float mn = fminf(fminf(fminf(cmn[k], mid[k]),
                                     fminf(cmn[k + 4], mid[k + 4])),
                               cmn[k + 2]);
        const float mx = fmaxf(fmaxf(fmaxf(cmx[k], mid[k]),
                                     fmaxf(cmx[k + 4], mid[k + 4])),
                               cmx[k + 2]);
        const float uw = fmaxf(p - mn, mx - p);     // == max_nb |p - nb|

        const float thred = (p >= 0.5f) ? p : 0.0f;
        uw_acc = fmaf(uw, thred, uw_acc);

        const float Lp = fmaxf(__log2f(p),        NEG100_LG2);
        const float L1 = fmaxf(__log2f(1.0f - p), NEG100_LG2);
        a_tLp = fmaf(t, Lp, a_tLp);
        a_tL1 = fmaf(t, L1, a_tL1);
        a_L1 += L1;
    }
}

__global__ __launch_bounds__(NTHREADS, 3)
void consistency_main(const float* __restrict__ yt, const float* __restrict__ yp,
                      float* __restrict__ out) {
    __shared__ float warp_sums[NTHREADS / 32];

    const int blk = blockIdx.x;                     // 0..1023
    const int b   = blk >> 6;                       // image
    const int yg  = (blk & (BLKS_PER_IMG - 1)) * RPB;
    const int tid = threadIdx.x;
    const int x4  = tid * 4;
    const bool leftEdge  = (tid == 0);
    const bool rightEdge = (tid == NTHREADS - 1);

    const float* img  = yp + (size_t)b * Hh * Ww;
    const float* timg = yt + (size_t)b * Hh * Ww;

    float uw_acc = 0.f, a_tLp = 0.f, a_tL1 = 0.f, a_L1 = 0.f;

    // Two parity chains; inner chain FULLY unrolled so rolling copies become
    // register renames and the 4 bodies overlap (ILP over MUFU/LDG latency).
#pragma unroll 1
    for (int c = 0; c < 2; ++c) {
        float w0[8], w1[8], w2[8], w3[8];
        load_winG(w0, img, yg + c - 2, x4, leftEdge, rightEdge);
        load_winG(w1, img, yg + c,     x4, leftEdge, rightEdge);

#pragma unroll
        for (int j = c; j < RPB; j += 4) {
            load_winG(w2, img, yg + j + 2, x4, leftEdge, rightEdge);
            load_winG(w3, img, yg + j + 4, x4, leftEdge, rightEdge);
            const float4 tA = *reinterpret_cast<const float4*>(
                timg + (size_t)(yg + j) * Ww + x4);
            const float4 tB = *reinterpret_cast<const float4*>(
                timg + (size_t)(yg + j + 2) * Ww + x4);

            row_loss(w0, w1, w2, tA, uw_acc, a_tLp, a_tL1, a_L1);   // row j
            row_loss(w1, w2, w3, tB, uw_acc, a_tLp, a_tL1, a_L1);   // row j+2

#pragma unroll
            for (int q = 0; q < 8; ++q) { w0[q] = w2[q]; w1[q] = w3[q]; }
        }
    }

    // bce_sum(lg2) = -(Σ t·Lp + Σ L1 - Σ t·L1); fold ln2 once.
    float lsum = fmaf(LN2F, a_tL1 - a_tLp - a_L1, uw_acc);

    // Block reduction
#pragma unroll
    for (int off = 16; off > 0; off >>= 1)
        lsum += __shfl_xor_sync(0xFFFFFFFFu, lsum, off);
    if ((tid & 31) == 0) warp_sums[tid >> 5] = lsum;
    __syncthreads();
    if (tid == 0) {
        float v = 0.f;
#pragma unroll
        for (int w = 0; w < NTHREADS / 32; ++w) v += warp_sums[w];

        // Fused final reduction: last-arriving block writes the mean.
        atomicAdd(&g_sum, (double)v);
        __threadfence();
        const unsigned int old = atomicAdd(&g_count, 1u);
        if (old == NBLOCKS - 1) {
            const double total = atomicAdd(&g_sum, 0.0);   // coherent read
            out[0] = (float)(total / (double)NELEM);
            g_sum   = 0.0;                                  // reset for next replay
            __threadfence();
            g_count = 0u;
        }
    }
}

extern "C" void kernel_launch(void* const* d_in, const int* in_sizes, int n_in,
                              void* d_out, int out_size) {
    const float* y_true = (const float*)d_in[0];
    const float* y_pred = (const float*)d_in[1];
    float* out = (float*)d_out;
    consistency_main<<<NBLOCKS, NTHREADS>>>(y_true, y_pred, out);
}